// round 2
// baseline (speedup 1.0000x reference)
#include <cuda_runtime.h>
#include <math.h>

#define Bn 16
#define Cn 192
#define HW 4096
#define CHW (Cn*HW)          // 786432
#define NPIX (Bn*CHW)        // 12582912
#define CPG 48
#define NGRP (CPG*HW)        // 196608

// Scratch (device globals: allocation-free rule)
__device__ float g_zconv[NPIX];             // depthwise conv output
__device__ float g_part[Bn*Cn*4*2];         // per-block (sum, sumsq) partials
__device__ float g_mu[64];
__device__ float g_rstd[64];

// ---------------------------------------------------------------------------
// Kernel 1: z = x + hidden, depthwise 7x7 'same' conv, per-block GN partials
// grid (B*C, 4 tiles of 32x32), block 256
// ---------------------------------------------------------------------------
__global__ __launch_bounds__(256) void conv_kernel(
    const float* __restrict__ x, const float* __restrict__ hid,
    const float* __restrict__ dww, const float* __restrict__ dwb)
{
    __shared__ float patch[38][40];
    __shared__ float wsm[49];
    __shared__ float redsum[8], redsq[8];

    int bc   = blockIdx.x;           // b*C + c
    int tile = blockIdx.y;           // 0..3
    int c    = bc % Cn;
    int ty0  = (tile >> 1) * 32, tx0 = (tile & 1) * 32;
    int base = bc * HW;
    int tid  = threadIdx.x;

    if (tid < 49) wsm[tid] = dww[c*49 + tid];

    for (int e = tid; e < 38*38; e += 256) {
        int py = e / 38, px = e % 38;
        int gy = ty0 + py - 3, gx = tx0 + px - 3;
        float v = 0.f;
        if (gy >= 0 && gy < 64 && gx >= 0 && gx < 64) {
            int gi = base + gy*64 + gx;
            v = x[gi] + hid[gi];
        }
        patch[py][px] = v;
    }
    __syncthreads();

    float bias = dwb[c];
    int lx = tid & 31, ly0 = tid >> 5;
    float s = 0.f, s2 = 0.f;
    #pragma unroll
    for (int r = 0; r < 4; r++) {
        int ly = ly0 + r*8;
        float acc = bias;
        #pragma unroll
        for (int ky = 0; ky < 7; ky++)
            #pragma unroll
            for (int kx = 0; kx < 7; kx++)
                acc += wsm[ky*7+kx] * patch[ly+ky][lx+kx];
        g_zconv[base + (ty0+ly)*64 + tx0 + lx] = acc;
        s += acc; s2 += acc*acc;
    }
    // deterministic fixed-order reduction
    #pragma unroll
    for (int o = 16; o > 0; o >>= 1) {
        s  += __shfl_xor_sync(~0u, s,  o);
        s2 += __shfl_xor_sync(~0u, s2, o);
    }
    if ((tid & 31) == 0) { redsum[tid>>5] = s; redsq[tid>>5] = s2; }
    __syncthreads();
    if (tid == 0) {
        float S = 0.f, S2 = 0.f;
        #pragma unroll
        for (int i = 0; i < 8; i++) { S += redsum[i]; S2 += redsq[i]; }
        int pi = (bc*4 + tile)*2;
        g_part[pi] = S; g_part[pi+1] = S2;
    }
}

// ---------------------------------------------------------------------------
// Kernel 2: finalize GN stats. grid 64 (b*4+g), block 256
// partials for group (b,g) are 192 consecutive tile-blocks at (b*C+g*48)*4
// ---------------------------------------------------------------------------
__global__ __launch_bounds__(256) void stats_kernel()
{
    __shared__ float ss[256], sq[256];
    int gidx = blockIdx.x;
    int b = gidx >> 2, g = gidx & 3;
    int base = (b*Cn + g*CPG) * 4 * 2;   // float offset
    int tid = threadIdx.x;
    float a = 0.f, q = 0.f;
    if (tid < 192) { a = g_part[base + tid*2]; q = g_part[base + tid*2 + 1]; }
    ss[tid] = a; sq[tid] = q;
    __syncthreads();
    for (int st = 128; st > 0; st >>= 1) {
        if (tid < st) { ss[tid] += ss[tid+st]; sq[tid] += sq[tid+st]; }
        __syncthreads();
    }
    if (tid == 0) {
        float inv = 1.0f / (float)NGRP;
        float mu  = ss[0] * inv;
        float var = sq[0] * inv - mu*mu;
        g_mu[gidx]   = mu;
        g_rstd[gidx] = rsqrtf(var + 1e-5f);
    }
}

// ---------------------------------------------------------------------------
// Kernel 3: fused GN-apply + FiLM + 1x1 conv GEMM (f32x2 FFMA2) + LSTM gates
// grid (HW/32, B), block 768. Each block: 32 pixels x all 768 outputs.
// Thread (c=tid>>2, tx=tid&3): 4 gates of channel c for 8 pixels (32 accs as
// 16 packed f32x2).
// ---------------------------------------------------------------------------
__device__ __forceinline__ unsigned long long ffma2(
    unsigned long long a, unsigned long long b, unsigned long long c)
{
    unsigned long long d;
    asm("fma.rn.f32x2 %0, %1, %2, %3;" : "=l"(d) : "l"(a), "l"(b), "l"(c));
    return d;
}
__device__ __forceinline__ unsigned long long pack2(float v)
{
    unsigned long long d; unsigned int u = __float_as_uint(v);
    asm("mov.b64 %0, {%1, %1};" : "=l"(d) : "r"(u));
    return d;
}
__device__ __forceinline__ float2 unpack2(unsigned long long v)
{
    float2 r;
    asm("mov.b64 {%0, %1}, %2;" : "=f"(r.x), "=f"(r.y) : "l"(v));
    return r;
}
__device__ __forceinline__ float sigm(float v){ return 1.0f/(1.0f + expf(-v)); }
__device__ __forceinline__ float gelu_exact(float v){
    return 0.5f*v*(1.0f + erff(v*0.70710678118654752f));
}

__global__ __launch_bounds__(768,1) void gemm_gates_kernel(
    const float* __restrict__ ctx, const float* __restrict__ cell,
    const float* __restrict__ pw,  const float* __restrict__ pwb,
    float* __restrict__ out)
{
    // 16B-aligned: zn_s is read with 64-bit LDS (offsets are even floats)
    __shared__ __align__(16) float zn_s[192*36]; // [k][p] stride 36 (pad)
    __shared__ __align__(16) float w_s[4*768];   // K-chunk of 4, all 768 rows

    int b    = blockIdx.y;
    int pix0 = blockIdx.x * 32;
    int tid  = threadIdx.x;

    // ---- load + normalize + FiLM into smem (context/conv read exactly once)
    const int cbase = b*CHW   + pix0;
    const int xbase = b*2*CHW + pix0;
    #pragma unroll
    for (int i = 0; i < 8; i++) {
        int e = tid + i*768;
        int k = e >> 5, p = e & 31;
        float conv = g_zconv[cbase + k*HW + p];
        float sc   = ctx[xbase + k*HW + p];
        float bi   = ctx[xbase + (Cn + k)*HW + p];
        int gi = (b << 2) + k/48;
        float zn = (conv - g_mu[gi]) * g_rstd[gi];
        zn_s[k*36 + p] = zn * (1.0f + sc) + bi;
    }
    __syncthreads();

    int c  = tid >> 2;
    int p0 = (tid & 3) * 8;

    unsigned long long acc[4][4];
    #pragma unroll
    for (int g = 0; g < 4; g++)
        #pragma unroll
        for (int j = 0; j < 4; j++) acc[g][j] = 0ull;

    for (int kc = 0; kc < 192; kc += 4) {
        if (kc) __syncthreads();
        // thread t owns weight row t: contiguous 16B read (L2-resident)
        float4 wv = *reinterpret_cast<const float4*>(pw + tid*192 + kc);
        w_s[0*768 + tid] = wv.x; w_s[1*768 + tid] = wv.y;
        w_s[2*768 + tid] = wv.z; w_s[3*768 + tid] = wv.w;
        __syncthreads();
        #pragma unroll
        for (int kk = 0; kk < 4; kk++) {
            int k = kc + kk;
            unsigned long long w2[4], z2[4];
            #pragma unroll
            for (int g = 0; g < 4; g++)
                w2[g] = pack2(w_s[kk*768 + c + 192*g]);
            #pragma unroll
            for (int j = 0; j < 4; j++)
                z2[j] = *reinterpret_cast<const unsigned long long*>(
                            &zn_s[k*36 + p0 + 2*j]);
            #pragma unroll
            for (int g = 0; g < 4; g++)
                #pragma unroll
                for (int j = 0; j < 4; j++)
                    acc[g][j] = ffma2(w2[g], z2[j], acc[g][j]);
        }
    }

    // ---- epilogue: LSTM gates + exact GELU, vectorized I/O
    float bf = pwb[c], bi2 = pwb[c+192], bg = pwb[c+384], bo = pwb[c+576];
    int idx0 = b*CHW + c*HW + pix0 + p0;
    float4 co0 = *reinterpret_cast<const float4*>(cell + idx0);
    float4 co1 = *reinterpret_cast<const float4*>(cell + idx0 + 4);
    float cold[8] = {co0.x,co0.y,co0.z,co0.w, co1.x,co1.y,co1.z,co1.w};
    float hn[8], cn[8];
    #pragma unroll
    for (int j = 0; j < 4; j++) {
        float2 fv = unpack2(acc[0][j]);
        float2 iv = unpack2(acc[1][j]);
        float2 gv = unpack2(acc[2][j]);
        float2 ov = unpack2(acc[3][j]);
        float fx[2] = {fv.x+bf,  fv.y+bf };
        float ix[2] = {iv.x+bi2, iv.y+bi2};
        float gx[2] = {gv.x+bg,  gv.y+bg };
        float ox[2] = {ov.x+bo,  ov.y+bo };
        #pragma unroll
        for (int t = 0; t < 2; t++) {
            int p = 2*j + t;
            float cv = sigm(fx[t])*cold[p] + sigm(ix[t])*tanhf(gx[t]);
            cn[p] = cv;
            hn[p] = sigm(ox[t]) * gelu_exact(cv);
        }
    }
    float4* oh = reinterpret_cast<float4*>(out + idx0);
    oh[0] = make_float4(hn[0],hn[1],hn[2],hn[3]);
    oh[1] = make_float4(hn[4],hn[5],hn[6],hn[7]);
    float4* oc = reinterpret_cast<float4*>(out + NPIX + idx0);
    oc[0] = make_float4(cn[0],cn[1],cn[2],cn[3]);
    oc[1] = make_float4(cn[4],cn[5],cn[6],cn[7]);
}

// ---------------------------------------------------------------------------
extern "C" void kernel_launch(void* const* d_in, const int* in_sizes, int n_in,
                              void* d_out, int out_size)
{
    const float* x      = (const float*)d_in[0];
    const float* hidden = (const float*)d_in[1];
    const float* cell   = (const float*)d_in[2];
    const float* ctx    = (const float*)d_in[3];
    const float* dww    = (const float*)d_in[4];
    const float* dwb    = (const float*)d_in[5];
    const float* pw     = (const float*)d_in[6];
    const float* pwb    = (const float*)d_in[7];
    float* out = (float*)d_out;

    conv_kernel<<<dim3(Bn*Cn, 4), 256>>>(x, hidden, dww, dwb);
    stats_kernel<<<64, 256>>>();
    gemm_gates_kernel<<<dim3(HW/32, Bn), 768>>>(ctx, cell, pw, pwb, out);
}

// round 3
// speedup vs baseline: 2.4239x; 2.4239x over previous
#include <cuda_runtime.h>
#include <math.h>

#define Bn 16
#define Cn 192
#define HW 4096
#define CHW (Cn*HW)          // 786432
#define NPIX (Bn*CHW)        // 12582912
#define CPG 48
#define NGRP (CPG*HW)        // 196608

// Scratch (device globals: allocation-free rule)
__device__ float g_zconv[NPIX];             // depthwise conv output
__device__ float g_zn[NPIX];                // GN+FiLM output, tf32-rounded
__device__ float g_wt[192*768];             // weights [k][ch*4+gate], tf32
__device__ float g_part[Bn*Cn*4*2];         // per-block (sum, sumsq) partials
__device__ float g_mu[64];
__device__ float g_rstd[64];

// ---------------------------------------------------------------------------
// Kernel 0: weight transpose/gather + tf32 round
// g_wt[k*768 + cc*4 + g] = tf32(pw[(g*192+cc)*192 + k])
// ---------------------------------------------------------------------------
__global__ __launch_bounds__(256) void setup_wt(const float* __restrict__ pw)
{
    int i = blockIdx.x*256 + threadIdx.x;
    if (i >= 192*768) return;
    int k = i / 768, o = i - k*768;
    int cc = o >> 2, g = o & 3;
    float v = pw[(g*192 + cc)*192 + k];
    unsigned r; asm("cvt.rna.tf32.f32 %0, %1;" : "=r"(r) : "f"(v));
    g_wt[i] = __uint_as_float(r);
}

// ---------------------------------------------------------------------------
// Kernel 1: z = x + hidden, depthwise 7x7 'same' conv, per-block GN partials
// ---------------------------------------------------------------------------
__global__ __launch_bounds__(256) void conv_kernel(
    const float* __restrict__ x, const float* __restrict__ hid,
    const float* __restrict__ dww, const float* __restrict__ dwb)
{
    __shared__ float patch[38][40];
    __shared__ float wsm[49];
    __shared__ float redsum[8], redsq[8];

    int bc   = blockIdx.x;           // b*C + c
    int tile = blockIdx.y;           // 0..3
    int c    = bc % Cn;
    int ty0  = (tile >> 1) * 32, tx0 = (tile & 1) * 32;
    int base = bc * HW;
    int tid  = threadIdx.x;

    if (tid < 49) wsm[tid] = dww[c*49 + tid];

    for (int e = tid; e < 38*38; e += 256) {
        int py = e / 38, px = e % 38;
        int gy = ty0 + py - 3, gx = tx0 + px - 3;
        float v = 0.f;
        if (gy >= 0 && gy < 64 && gx >= 0 && gx < 64) {
            int gi = base + gy*64 + gx;
            v = x[gi] + hid[gi];
        }
        patch[py][px] = v;
    }
    __syncthreads();

    float bias = dwb[c];
    int lx = tid & 31, ly0 = tid >> 5;
    float s = 0.f, s2 = 0.f;
    #pragma unroll
    for (int r = 0; r < 4; r++) {
        int ly = ly0 + r*8;
        float acc = bias;
        #pragma unroll
        for (int ky = 0; ky < 7; ky++)
            #pragma unroll
            for (int kx = 0; kx < 7; kx++)
                acc += wsm[ky*7+kx] * patch[ly+ky][lx+kx];
        g_zconv[base + (ty0+ly)*64 + tx0 + lx] = acc;
        s += acc; s2 += acc*acc;
    }
    #pragma unroll
    for (int o = 16; o > 0; o >>= 1) {
        s  += __shfl_xor_sync(~0u, s,  o);
        s2 += __shfl_xor_sync(~0u, s2, o);
    }
    if ((tid & 31) == 0) { redsum[tid>>5] = s; redsq[tid>>5] = s2; }
    __syncthreads();
    if (tid == 0) {
        float S = 0.f, S2 = 0.f;
        #pragma unroll
        for (int i = 0; i < 8; i++) { S += redsum[i]; S2 += redsq[i]; }
        int pi = (bc*4 + tile)*2;
        g_part[pi] = S; g_part[pi+1] = S2;
    }
}

// ---------------------------------------------------------------------------
// Kernel 2: finalize GN stats
// ---------------------------------------------------------------------------
__global__ __launch_bounds__(256) void stats_kernel()
{
    __shared__ float ss[256], sq[256];
    int gidx = blockIdx.x;
    int b = gidx >> 2, g = gidx & 3;
    int base = (b*Cn + g*CPG) * 4 * 2;
    int tid = threadIdx.x;
    float a = 0.f, q = 0.f;
    if (tid < 192) { a = g_part[base + tid*2]; q = g_part[base + tid*2 + 1]; }
    ss[tid] = a; sq[tid] = q;
    __syncthreads();
    for (int st = 128; st > 0; st >>= 1) {
        if (tid < st) { ss[tid] += ss[tid+st]; sq[tid] += sq[tid+st]; }
        __syncthreads();
    }
    if (tid == 0) {
        float inv = 1.0f / (float)NGRP;
        float mu  = ss[0] * inv;
        float var = sq[0] * inv - mu*mu;
        g_mu[gidx]   = mu;
        g_rstd[gidx] = rsqrtf(var + 1e-5f);
    }
}

// ---------------------------------------------------------------------------
// Kernel 3: apply GN + FiLM, tf32-round, write g_zn (elementwise, float4)
// ---------------------------------------------------------------------------
__global__ __launch_bounds__(256) void apply_kernel(const float* __restrict__ ctx)
{
    int i4 = blockIdx.x*256 + threadIdx.x;
    int e = i4 << 2;
    if (e >= NPIX) return;
    int b  = e / CHW;
    int r  = e - b*CHW;
    int c  = r / HW;
    int hw = r - c*HW;
    int gi = (b << 2) + c / CPG;
    float mu = g_mu[gi], rs = g_rstd[gi];
    float4 cv = *reinterpret_cast<const float4*>(g_zconv + e);
    const float* cb = ctx + b*2*CHW + c*HW + hw;
    float4 sc = *reinterpret_cast<const float4*>(cb);
    float4 bi = *reinterpret_cast<const float4*>(cb + CHW);
    float o0 = (cv.x - mu)*rs*(1.f+sc.x) + bi.x;
    float o1 = (cv.y - mu)*rs*(1.f+sc.y) + bi.y;
    float o2 = (cv.z - mu)*rs*(1.f+sc.z) + bi.z;
    float o3 = (cv.w - mu)*rs*(1.f+sc.w) + bi.w;
    unsigned u0,u1,u2,u3;
    asm("cvt.rna.tf32.f32 %0, %1;" : "=r"(u0) : "f"(o0));
    asm("cvt.rna.tf32.f32 %0, %1;" : "=r"(u1) : "f"(o1));
    asm("cvt.rna.tf32.f32 %0, %1;" : "=r"(u2) : "f"(o2));
    asm("cvt.rna.tf32.f32 %0, %1;" : "=r"(u3) : "f"(o3));
    float4 ov = make_float4(__uint_as_float(u0), __uint_as_float(u1),
                            __uint_as_float(u2), __uint_as_float(u3));
    *reinterpret_cast<float4*>(g_zn + e) = ov;
}

// ---------------------------------------------------------------------------
// Kernel 4: tensor-core GEMM (tf32 mma.sync) + fused LSTM gates
// block: 128 pixels x 256 gathered outputs (64 ch x 4 gates), 512 thr (4x4 warps)
// warp tile 64x32, K=192 in 12 double-buffered k16 chunks
// ---------------------------------------------------------------------------
#define PT   128
#define ZSTR 136   // 136 mod 32 = 8 -> conflict-free B-frag LDS
#define ASTR 264   // 264 mod 32 = 8 -> conflict-free A-frag LDS
#define DSTR 260   // 260 mod 32 = 4 -> conflict-free epilogue store + LDS.128

__device__ __forceinline__ void mma_tf32(
    float d[4], unsigned a0, unsigned a1, unsigned a2, unsigned a3,
    unsigned b0, unsigned b1)
{
    asm volatile(
        "mma.sync.aligned.m16n8k8.row.col.f32.tf32.tf32.f32 "
        "{%0,%1,%2,%3}, {%4,%5,%6,%7}, {%8,%9}, {%0,%1,%2,%3};"
        : "+f"(d[0]), "+f"(d[1]), "+f"(d[2]), "+f"(d[3])
        : "r"(a0), "r"(a1), "r"(a2), "r"(a3), "r"(b0), "r"(b1));
}
__device__ __forceinline__ float sigm(float v){ return 1.0f/(1.0f + expf(-v)); }
__device__ __forceinline__ float gelu_exact(float v){
    return 0.5f*v*(1.0f + erff(v*0.70710678118654752f));
}

__global__ __launch_bounds__(512,1) void gemm_kernel(
    const float* __restrict__ cell, const float* __restrict__ pwb,
    float* __restrict__ out)
{
    extern __shared__ float sm[];
    float* zn_s = sm;                 // [192][ZSTR]
    float* a_s  = sm + 192*ZSTR;      // [2][16][ASTR]
    float* d_s  = sm;                 // epilogue [64 pix][DSTR rows], reuses zn

    int tid  = threadIdx.x;
    int cb   = blockIdx.y * 64;       // channel base (0/64/128)
    int pixg = blockIdx.x * PT;
    int b    = pixg / HW;
    int hw0  = pixg - b*HW;

    // ---- stage zn tile [192 k][128 px]
    {
        const float* src = g_zn + b*CHW + hw0;
        #pragma unroll
        for (int it = 0; it < 12; it++) {
            int i = tid + it*512;               // over 192*32 float4s
            int k = i >> 5, p4 = (i & 31) << 2;
            float4 v = *reinterpret_cast<const float4*>(src + k*HW + p4);
            *reinterpret_cast<float4*>(zn_s + k*ZSTR + p4) = v;
        }
    }

    int wid = tid >> 5, l = tid & 31;
    int wm = wid & 3, wn = wid >> 2;
    int g  = l >> 2, t = l & 3;

    float D[4][4][4];
    #pragma unroll
    for (int i = 0; i < 4; i++)
        #pragma unroll
        for (int j = 0; j < 4; j++)
            #pragma unroll
            for (int q = 0; q < 4; q++) D[i][j][q] = 0.f;

    // weight chunk loader: thread -> (kk = tid>>5, r0 = (tid&31)*8)
    int wkk = tid >> 5;
    int wr0 = l << 3;
    {
        const float* srcw = g_wt + wkk*768 + cb*4 + wr0;
        float4 v0 = *reinterpret_cast<const float4*>(srcw);
        float4 v1 = *reinterpret_cast<const float4*>(srcw + 4);
        float* d = a_s + wkk*ASTR + wr0;
        *reinterpret_cast<float4*>(d)     = v0;
        *reinterpret_cast<float4*>(d + 4) = v1;
    }
    __syncthreads();

    for (int kc = 0; kc < 12; kc++) {
        // prefetch next chunk into other buffer
        if (kc + 1 < 12) {
            const float* srcw = g_wt + ((kc+1)*16 + wkk)*768 + cb*4 + wr0;
            float4 v0 = *reinterpret_cast<const float4*>(srcw);
            float4 v1 = *reinterpret_cast<const float4*>(srcw + 4);
            float* d = a_s + ((kc+1)&1)*16*ASTR + wkk*ASTR + wr0;
            *reinterpret_cast<float4*>(d)     = v0;
            *reinterpret_cast<float4*>(d + 4) = v1;
        }
        const float* ab = a_s + (kc&1)*16*ASTR;
        #pragma unroll
        for (int ks = 0; ks < 2; ks++) {
            int k0 = ks*8;
            int kg = kc*16 + k0 + t;
            unsigned Bf[4][2];
            #pragma unroll
            for (int tn = 0; tn < 4; tn++) {
                int p = wn*32 + tn*8 + g;
                Bf[tn][0] = __float_as_uint(zn_s[ kg   *ZSTR + p]);
                Bf[tn][1] = __float_as_uint(zn_s[(kg+4)*ZSTR + p]);
            }
            #pragma unroll
            for (int tm = 0; tm < 4; tm++) {
                int r = wm*64 + tm*16 + g;
                unsigned a0 = __float_as_uint(ab[(k0+t  )*ASTR + r    ]);
                unsigned a1 = __float_as_uint(ab[(k0+t  )*ASTR + r + 8]);
                unsigned a2 = __float_as_uint(ab[(k0+t+4)*ASTR + r    ]);
                unsigned a3 = __float_as_uint(ab[(k0+t+4)*ASTR + r + 8]);
                #pragma unroll
                for (int tn = 0; tn < 4; tn++)
                    mma_tf32(D[tm][tn], a0, a1, a2, a3, Bf[tn][0], Bf[tn][1]);
            }
        }
        __syncthreads();
    }

    // ---- epilogue: two halves of 64 pixels (d_s reuses zn_s space)
    int ch = tid & 63;            // local channel
    int p8 = tid >> 6;            // 0..7 -> 8 pixels each
    int cc = cb + ch;
    float bf  = pwb[cc];
    float bi_ = pwb[192 + cc];
    float bg  = pwb[384 + cc];
    float bo  = pwb[576 + cc];

    #pragma unroll
    for (int h = 0; h < 2; h++) {
        if ((wn >> 1) == h) {
            int wn2 = wn & 1;
            #pragma unroll
            for (int tm = 0; tm < 4; tm++)
                #pragma unroll
                for (int tn = 0; tn < 4; tn++) {
                    int row = wm*64 + tm*16 + g;
                    int col = wn2*32 + tn*8 + 2*t;
                    d_s[ col   *DSTR + row    ] = D[tm][tn][0];
                    d_s[(col+1)*DSTR + row    ] = D[tm][tn][1];
                    d_s[ col   *DSTR + row + 8] = D[tm][tn][2];
                    d_s[(col+1)*DSTR + row + 8] = D[tm][tn][3];
                }
        }
        __syncthreads();

        int hwb  = hw0 + h*64 + p8*8;
        int base = b*CHW + cc*HW + hwb;
        float4 c0 = *reinterpret_cast<const float4*>(cell + base);
        float4 c1 = *reinterpret_cast<const float4*>(cell + base + 4);
        float cold[8] = {c0.x,c0.y,c0.z,c0.w, c1.x,c1.y,c1.z,c1.w};
        float hn[8], cn[8];
        #pragma unroll
        for (int j = 0; j < 8; j++) {
            int pl = p8*8 + j;
            float4 gv = *reinterpret_cast<const float4*>(d_s + pl*DSTR + ch*4);
            float fv = gv.x + bf, iv = gv.y + bi_;
            float gg = gv.z + bg, ov = gv.w + bo;
            float cvv = sigm(fv)*cold[j] + sigm(iv)*tanhf(gg);
            cn[j] = cvv;
            hn[j] = sigm(ov) * gelu_exact(cvv);
        }
        float4* oh = reinterpret_cast<float4*>(out + base);
        oh[0] = make_float4(hn[0],hn[1],hn[2],hn[3]);
        oh[1] = make_float4(hn[4],hn[5],hn[6],hn[7]);
        float4* oc = reinterpret_cast<float4*>(out + NPIX + base);
        oc[0] = make_float4(cn[0],cn[1],cn[2],cn[3]);
        oc[1] = make_float4(cn[4],cn[5],cn[6],cn[7]);
        __syncthreads();
    }
}

// ---------------------------------------------------------------------------
extern "C" void kernel_launch(void* const* d_in, const int* in_sizes, int n_in,
                              void* d_out, int out_size)
{
    const float* x      = (const float*)d_in[0];
    const float* hidden = (const float*)d_in[1];
    const float* cell   = (const float*)d_in[2];
    const float* ctx    = (const float*)d_in[3];
    const float* dww    = (const float*)d_in[4];
    const float* dwb    = (const float*)d_in[5];
    const float* pw     = (const float*)d_in[6];
    const float* pwb    = (const float*)d_in[7];
    float* out = (float*)d_out;

    const int gemm_smem = (192*ZSTR + 2*16*ASTR) * 4;   // 138240 B
    cudaFuncSetAttribute(gemm_kernel,
                         cudaFuncAttributeMaxDynamicSharedMemorySize, gemm_smem);

    setup_wt<<<576, 256>>>(pw);
    conv_kernel<<<dim3(Bn*Cn, 4), 256>>>(x, hidden, dww, dwb);
    stats_kernel<<<64, 256>>>();
    apply_kernel<<<NPIX/4/256, 256>>>(ctx);
    gemm_kernel<<<dim3(Bn*HW/PT, 3), 512, gemm_smem>>>(cell, pwb, out);
}

// round 5
// speedup vs baseline: 3.2716x; 1.3497x over previous
#include <cuda_runtime.h>
#include <math.h>

#define Bn 16
#define Cn 192
#define HW 4096
#define CHW (Cn*HW)          // 786432
#define NPIX (Bn*CHW)        // 12582912
#define CPG 48
#define NGRP (CPG*HW)        // 196608

// Scratch (device globals: allocation-free rule)
__device__ float g_zconv[NPIX];          // depthwise conv output
__device__ float g_wfrag[768*192];       // fragment-packed weights, tf32
__device__ float g_part[Bn*Cn*4*2];      // per-block (sum, sumsq) partials
__device__ float g_mu[64];
__device__ float g_rstd[64];

__device__ __forceinline__ unsigned smem_u32(const void* p){
    unsigned a;
    asm("{ .reg .u64 t; cvta.to.shared.u64 t, %1; cvt.u32.u64 %0, t; }"
        : "=r"(a) : "l"(p));
    return a;
}
__device__ __forceinline__ float sigm_f(float v){
    return __fdividef(1.0f, 1.0f + __expf(-v));
}
__device__ __forceinline__ float tanh_f(float v){
    float a = __expf(2.0f*v);
    return 1.0f - __fdividef(2.0f, a + 1.0f);
}
__device__ __forceinline__ float gelu_exact(float v){
    return 0.5f*v*(1.0f + erff(v*0.70710678118654752f));
}
__device__ __forceinline__ void mma_tf32(float d[4], float4 A, float2 B){
    asm volatile("mma.sync.aligned.m16n8k8.row.col.f32.tf32.tf32.f32 "
        "{%0,%1,%2,%3}, {%4,%5,%6,%7}, {%8,%9}, {%0,%1,%2,%3};"
        : "+f"(d[0]), "+f"(d[1]), "+f"(d[2]), "+f"(d[3])
        : "r"(__float_as_uint(A.x)), "r"(__float_as_uint(A.y)),
          "r"(__float_as_uint(A.z)), "r"(__float_as_uint(A.w)),
          "r"(__float_as_uint(B.x)), "r"(__float_as_uint(B.y)));
}

// ---------------------------------------------------------------------------
// Kernel 0: pack weights in mma A-fragment order, tf32-rounded.
// float4 index i4 = (rb*24 + s)*128 + tm*32 + l :
//   {w(k0+t, r0), w(k0+t, r0+8), w(k0+t+4, r0), w(k0+t+4, r0+8)}
// with k0=s*8, r0=rb*64+tm*16+g, g=l>>2, t=l&3, row=ch*4+gate.
// ---------------------------------------------------------------------------
__global__ __launch_bounds__(256) void setup_wt(const float* __restrict__ pw)
{
    int i4 = blockIdx.x*256 + threadIdx.x;
    if (i4 >= 36864) return;
    int rb  = i4 / 3072;
    int rem = i4 - rb*3072;
    int s   = rem >> 7;
    int q   = rem & 127;
    int tm  = q >> 5, l = q & 31;
    int g = l >> 2, t = l & 3;
    int k0 = s*8;
    int r0 = rb*64 + tm*16 + g;
    float4 F;
    {
        int ks[4] = {k0+t, k0+t, k0+t+4, k0+t+4};
        int rs[4] = {r0, r0+8, r0, r0+8};
        float vv[4];
        #pragma unroll
        for (int j = 0; j < 4; j++) {
            int ch = rs[j] >> 2, gate = rs[j] & 3;
            float v = pw[(gate*192 + ch)*192 + ks[j]];
            unsigned u; asm("cvt.rna.tf32.f32 %0, %1;" : "=r"(u) : "f"(v));
            vv[j] = __uint_as_float(u);
        }
        F = make_float4(vv[0], vv[1], vv[2], vv[3]);
    }
    reinterpret_cast<float4*>(g_wfrag)[i4] = F;
}

// ---------------------------------------------------------------------------
// Kernel 1: z = x + hidden, depthwise 7x7 conv, per-block GN partials.
// Thread computes 4 horizontal outputs; patch rows read via LDS.128 windows.
// ---------------------------------------------------------------------------
__global__ __launch_bounds__(256) void conv_kernel(
    const float* __restrict__ x, const float* __restrict__ hid,
    const float* __restrict__ dww, const float* __restrict__ dwb)
{
    __shared__ __align__(16) float patch[38][44];
    __shared__ float wsm[49];
    __shared__ float redsum[8], redsq[8];

    int bc   = blockIdx.x;
    int tile = blockIdx.y;
    int c    = bc % Cn;
    int ty0  = (tile >> 1) * 32, tx0 = (tile & 1) * 32;
    int base = bc * HW;
    int tid  = threadIdx.x;

    if (tid < 49) wsm[tid] = dww[c*49 + tid];

    for (int e = tid; e < 38*44; e += 256) {
        int py = e / 44, px = e - py*44;
        int gy = ty0 + py - 3, gx = tx0 + px - 3;
        float v = 0.f;
        if (px < 38 && gy >= 0 && gy < 64 && gx >= 0 && gx < 64) {
            int gi = base + gy*64 + gx;
            v = x[gi] + hid[gi];
        }
        patch[py][px] = v;
    }
    __syncthreads();

    float w[49];
    #pragma unroll
    for (int i = 0; i < 49; i++) w[i] = wsm[i];

    int y  = tid >> 3;
    int x0 = (tid & 7) << 2;
    float bias = dwb[c];
    float a0 = bias, a1 = bias, a2 = bias, a3 = bias;

    #pragma unroll
    for (int ky = 0; ky < 7; ky++) {
        const float* pr = &patch[y + ky][x0];
        float4 q0 = *reinterpret_cast<const float4*>(pr);
        float4 q1 = *reinterpret_cast<const float4*>(pr + 4);
        float4 q2 = *reinterpret_cast<const float4*>(pr + 8);
        float e[10] = {q0.x,q0.y,q0.z,q0.w, q1.x,q1.y,q1.z,q1.w, q2.x,q2.y};
        #pragma unroll
        for (int kx = 0; kx < 7; kx++) {
            float wv = w[ky*7 + kx];
            a0 += wv*e[kx];   a1 += wv*e[kx+1];
            a2 += wv*e[kx+2]; a3 += wv*e[kx+3];
        }
    }

    *reinterpret_cast<float4*>(g_zconv + base + (ty0+y)*64 + tx0 + x0) =
        make_float4(a0, a1, a2, a3);

    float s  = a0 + a1 + a2 + a3;
    float s2 = a0*a0 + a1*a1 + a2*a2 + a3*a3;
    #pragma unroll
    for (int o = 16; o > 0; o >>= 1) {
        s  += __shfl_xor_sync(~0u, s,  o);
        s2 += __shfl_xor_sync(~0u, s2, o);
    }
    if ((tid & 31) == 0) { redsum[tid>>5] = s; redsq[tid>>5] = s2; }
    __syncthreads();
    if (tid == 0) {
        float S = 0.f, S2 = 0.f;
        #pragma unroll
        for (int i = 0; i < 8; i++) { S += redsum[i]; S2 += redsq[i]; }
        int pi = (bc*4 + tile)*2;
        g_part[pi] = S; g_part[pi+1] = S2;
    }
}

// ---------------------------------------------------------------------------
// Kernel 2: finalize GN stats
// ---------------------------------------------------------------------------
__global__ __launch_bounds__(256) void stats_kernel()
{
    __shared__ float ss[256], sq[256];
    int gidx = blockIdx.x;
    int b = gidx >> 2, g = gidx & 3;
    int base = (b*Cn + g*CPG) * 4 * 2;
    int tid = threadIdx.x;
    float a = 0.f, q = 0.f;
    if (tid < 192) { a = g_part[base + tid*2]; q = g_part[base + tid*2 + 1]; }
    ss[tid] = a; sq[tid] = q;
    __syncthreads();
    for (int st = 128; st > 0; st >>= 1) {
        if (tid < st) { ss[tid] += ss[tid+st]; sq[tid] += sq[tid+st]; }
        __syncthreads();
    }
    if (tid == 0) {
        float inv = 1.0f / (float)NGRP;
        float mu  = ss[0] * inv;
        float var = sq[0] * inv - mu*mu;
        g_mu[gidx]   = mu;
        g_rstd[gidx] = rsqrtf(var + 1e-5f);
    }
}

// ---------------------------------------------------------------------------
// Kernel 3: mma.sync tf32 GEMM, fragment-packed feeds, fused GN/FiLM staging
// + LSTM epilogue. Block = 128 px x 768 rows, 512 thr (16 warps).
// ---------------------------------------------------------------------------
#define WB      98304            // znp: [24 s][128 p][4 t] float2 = 98304 B
#define WBUFSZ  32768            // one k32 weight chunk (2048 float4)
#define EPI     (WB + 2*WBUFSZ)  // 163840
#define EPISTR  268
#define GSMEM   (EPI + 32*EPISTR*4)   // 198144

__global__ __launch_bounds__(512,1) void gemm_kernel(
    const float* __restrict__ ctx, const float* __restrict__ cell,
    const float* __restrict__ pwb, float* __restrict__ out)
{
    extern __shared__ __align__(16) char smem[];
    int tid = threadIdx.x;
    int b   = blockIdx.x >> 5;
    int hw0 = (blockIdx.x & 31) << 7;
    int wid = tid >> 5, l = tid & 31;
    int g = l >> 2, t4 = l & 3;
    int wm = wid & 3, wn = wid >> 2;

    // ---- stage znp: zn pairs (k, k+4), GN+FiLM fused, tf32-rounded ----
    {
        int px = tid >> 2;
        int tt = tid & 3;
        const float* zc = g_zconv + (size_t)b*CHW + hw0 + px;
        const float* cs = ctx + (size_t)b*2*CHW + hw0 + px;
        #pragma unroll 4
        for (int i = 0; i < 48; i++) {
            int k = tt + i*4;
            float conv = zc[(size_t)k*HW];
            float sc   = cs[(size_t)k*HW];
            float bi   = cs[(size_t)(k + Cn)*HW];
            int gi = (b << 2) + k/CPG;
            float zn = (conv - g_mu[gi])*g_rstd[gi]*(1.0f + sc) + bi;
            unsigned u; asm("cvt.rna.tf32.f32 %0, %1;" : "=r"(u) : "f"(zn));
            int s = k >> 3, h = (k >> 2) & 1;
            reinterpret_cast<float*>(smem)[((s*128 + px)*4 + tt)*2 + h] =
                __uint_as_float(u);
        }
    }

    // ---- prologue: cp.async weight chunk 0 ----
    #pragma unroll
    for (int f = 0; f < 4; f++) {
        int il = tid + f*512;
        int rbl = il >> 9, sh = (il >> 7) & 3, q = il & 127;
        const float4* src = reinterpret_cast<const float4*>(g_wfrag)
                          + (size_t)(rbl*24 + sh)*128 + q;
        unsigned sa = smem_u32(smem + WB + il*16);
        asm volatile("cp.async.cg.shared.global [%0], [%1], 16;"
                     :: "r"(sa), "l"(src));
    }
    asm volatile("cp.async.commit_group;" ::: "memory");

    float D[4][4][4];
    #pragma unroll
    for (int i = 0; i < 4; i++)
        #pragma unroll
        for (int j = 0; j < 4; j++)
            #pragma unroll
            for (int q = 0; q < 4; q++) D[i][j][q] = 0.f;

    for (int gc = 0; gc < 18; gc++) {
        asm volatile("cp.async.wait_group 0;" ::: "memory");
        __syncthreads();
        if (gc + 1 < 18) {
            int g2 = gc + 1;
            int segn = g2/6, ccn = g2 - segn*6;
            #pragma unroll
            for (int f = 0; f < 4; f++) {
                int il = tid + f*512;
                int rbl = il >> 9, sh = (il >> 7) & 3, q = il & 127;
                const float4* src = reinterpret_cast<const float4*>(g_wfrag)
                    + (size_t)((segn*4 + rbl)*24 + ccn*4 + sh)*128 + q;
                unsigned sa = smem_u32(smem + WB + (g2&1)*WBUFSZ + il*16);
                asm volatile("cp.async.cg.shared.global [%0], [%1], 16;"
                             :: "r"(sa), "l"(src));
            }
            asm volatile("cp.async.commit_group;" ::: "memory");
        }
        int cc = gc % 6;
        const char* wb = smem + WB + (gc&1)*WBUFSZ;
        #pragma unroll
        for (int sh = 0; sh < 4; sh++) {
            int s = cc*4 + sh;
            float2 Bf[4];
            #pragma unroll
            for (int tn = 0; tn < 4; tn++) {
                int p = wn*32 + tn*8 + g;
                Bf[tn] = *reinterpret_cast<const float2*>(
                            smem + ((s*128 + p)*4 + t4)*8);
            }
            #pragma unroll
            for (int tm = 0; tm < 4; tm++) {
                float4 A = *reinterpret_cast<const float4*>(
                            wb + ((wm*4 + sh)*128 + tm*32 + l)*16);
                #pragma unroll
                for (int tn = 0; tn < 4; tn++)
                    mma_tf32(D[tm][tn], A, Bf[tn]);
            }
        }

        if (cc == 5) {
            // ---- epilogue for seg = gc/6: 4 pixel phases of 32 ----
            int seg = gc / 6;
            float* ep = reinterpret_cast<float*>(smem + EPI);
            int chl = tid >> 3;           // 0..63
            int pq  = tid & 7;            // 0..7 -> 4 px each
            int ch  = seg*64 + chl;
            float bfc = pwb[ch], bic = pwb[192+ch];
            float bgc = pwb[384+ch], boc = pwb[576+ch];
            #pragma unroll 1
            for (int ph = 0; ph < 4; ph++) {
                if (wn == ph) {
                    #pragma unroll
                    for (int tm = 0; tm < 4; tm++)
                        #pragma unroll
                        for (int tn = 0; tn < 4; tn++) {
                            int row = wm*64 + tm*16 + g;
                            int px  = tn*8 + 2*t4;
                            ep[ px   *EPISTR + row    ] = D[tm][tn][0];
                            ep[(px+1)*EPISTR + row    ] = D[tm][tn][1];
                            ep[ px   *EPISTR + row + 8] = D[tm][tn][2];
                            ep[(px+1)*EPISTR + row + 8] = D[tm][tn][3];
                        }
                }
                __syncthreads();
                size_t gbase = (size_t)b*CHW + (size_t)ch*HW
                             + hw0 + ph*32 + pq*4;
                float4 co = *reinterpret_cast<const float4*>(cell + gbase);
                float cold[4] = {co.x, co.y, co.z, co.w};
                float hn[4], cn[4];
                #pragma unroll
                for (int j = 0; j < 4; j++) {
                    float4 gv = *reinterpret_cast<const float4*>(
                                ep + (pq*4 + j)*EPISTR + chl*4);
                    float fv = gv.x + bfc, iv = gv.y + bic;
                    float gg = gv.z + bgc, ov = gv.w + boc;
                    float cv = sigm_f(fv)*cold[j] + sigm_f(iv)*tanh_f(gg);
                    cn[j] = cv;
                    hn[j] = sigm_f(ov) * gelu_exact(cv);
                }
                *reinterpret_cast<float4*>(out + gbase) =
                    make_float4(hn[0], hn[1], hn[2], hn[3]);
                *reinterpret_cast<float4*>(out + NPIX + gbase) =
                    make_float4(cn[0], cn[1], cn[2], cn[3]);
                __syncthreads();
            }
            // reset accumulators for next seg
            #pragma unroll
            for (int i = 0; i < 4; i++)
                #pragma unroll
                for (int j = 0; j < 4; j++)
                    #pragma unroll
                    for (int q = 0; q < 4; q++) D[i][j][q] = 0.f;
        }
    }
}

// ---------------------------------------------------------------------------
extern "C" void kernel_launch(void* const* d_in, const int* in_sizes, int n_in,
                              void* d_out, int out_size)
{
    const float* x      = (const float*)d_in[0];
    const float* hidden = (const float*)d_in[1];
    const float* cell   = (const float*)d_in[2];
    const float* ctx    = (const float*)d_in[3];
    const float* dww    = (const float*)d_in[4];
    const float* dwb    = (const float*)d_in[5];
    const float* pw     = (const float*)d_in[6];
    const float* pwb    = (const float*)d_in[7];
    float* out = (float*)d_out;

    cudaFuncSetAttribute(gemm_kernel,
                         cudaFuncAttributeMaxDynamicSharedMemorySize, GSMEM);

    setup_wt<<<144, 256>>>(pw);
    conv_kernel<<<dim3(Bn*Cn, 4), 256>>>(x, hidden, dww, dwb);
    stats_kernel<<<64, 256>>>();
    gemm_kernel<<<512, 512, GSMEM>>>(ctx, cell, pwb, out);
}

// round 6
// speedup vs baseline: 3.3872x; 1.0353x over previous
#include <cuda_runtime.h>
#include <math.h>

#define Bn 16
#define Cn 192
#define HW 4096
#define CHW (Cn*HW)          // 786432
#define NPIX (Bn*CHW)        // 12582912
#define CPG 48
#define NGRP (CPG*HW)        // 196608

// Scratch (device globals: allocation-free rule)
__device__ float g_zconv[NPIX];          // depthwise conv output
__device__ float g_wfrag[768*192];       // fragment-packed weights, tf32
__device__ float g_part[Bn*Cn*4*2];      // per-block (sum, sumsq) partials
__device__ float g_mu[64];
__device__ float g_rstd[64];

__device__ __forceinline__ unsigned smem_u32(const void* p){
    unsigned a;
    asm("{ .reg .u64 t; cvta.to.shared.u64 t, %1; cvt.u32.u64 %0, t; }"
        : "=r"(a) : "l"(p));
    return a;
}
__device__ __forceinline__ float sigm_f(float v){
    return __fdividef(1.0f, 1.0f + __expf(-v));
}
__device__ __forceinline__ float tanh_f(float v){
    float a = __expf(2.0f*v);
    return 1.0f - __fdividef(2.0f, a + 1.0f);
}
__device__ __forceinline__ float gelu_exact(float v){
    return 0.5f*v*(1.0f + erff(v*0.70710678118654752f));
}
__device__ __forceinline__ void mma_tf32(float d[4], float4 A, float2 B){
    asm volatile("mma.sync.aligned.m16n8k8.row.col.f32.tf32.tf32.f32 "
        "{%0,%1,%2,%3}, {%4,%5,%6,%7}, {%8,%9}, {%0,%1,%2,%3};"
        : "+f"(d[0]), "+f"(d[1]), "+f"(d[2]), "+f"(d[3])
        : "r"(__float_as_uint(A.x)), "r"(__float_as_uint(A.y)),
          "r"(__float_as_uint(A.z)), "r"(__float_as_uint(A.w)),
          "r"(__float_as_uint(B.x)), "r"(__float_as_uint(B.y)));
}

// ---------------------------------------------------------------------------
// Kernel 0: pack weights in mma A-fragment order, tf32-rounded.
// ---------------------------------------------------------------------------
__global__ __launch_bounds__(256) void setup_wt(const float* __restrict__ pw)
{
    int i4 = blockIdx.x*256 + threadIdx.x;
    if (i4 >= 36864) return;
    int rb  = i4 / 3072;
    int rem = i4 - rb*3072;
    int s   = rem >> 7;
    int q   = rem & 127;
    int tm  = q >> 5, l = q & 31;
    int g = l >> 2, t = l & 3;
    int k0 = s*8;
    int r0 = rb*64 + tm*16 + g;
    float4 F;
    {
        int ks[4] = {k0+t, k0+t, k0+t+4, k0+t+4};
        int rs[4] = {r0, r0+8, r0, r0+8};
        float vv[4];
        #pragma unroll
        for (int j = 0; j < 4; j++) {
            int ch = rs[j] >> 2, gate = rs[j] & 3;
            float v = pw[(gate*192 + ch)*192 + ks[j]];
            unsigned u; asm("cvt.rna.tf32.f32 %0, %1;" : "=r"(u) : "f"(v));
            vv[j] = __uint_as_float(u);
        }
        F = make_float4(vv[0], vv[1], vv[2], vv[3]);
    }
    reinterpret_cast<float4*>(g_wfrag)[i4] = F;
}

// ---------------------------------------------------------------------------
// Kernel 1: z = x + hidden, depthwise 7x7 conv, per-strip GN partials.
// Tile 64w x 32h, 256 thr. Thread computes 4x2 outputs; 8 shared patch rows.
// grid (B*C, 2)
// ---------------------------------------------------------------------------
__global__ __launch_bounds__(256) void conv_kernel(
    const float* __restrict__ x, const float* __restrict__ hid,
    const float* __restrict__ dww, const float* __restrict__ dwb)
{
    __shared__ __align__(16) float patch[38][72];
    __shared__ float wsm[49];
    __shared__ float redsum[8], redsq[8];

    int bc    = blockIdx.x;
    int strip = blockIdx.y;          // 0..1 : rows strip*32..+31
    int c     = bc % Cn;
    int ty0   = strip * 32;
    int base  = bc * HW;
    int tid   = threadIdx.x;

    if (tid < 49) wsm[tid] = dww[c*49 + tid];

    for (int e = tid; e < 38*72; e += 256) {
        int py = e / 72, px = e - py*72;
        int gy = ty0 + py - 3, gx = px - 3;
        float v = 0.f;
        if (px < 70 && gy >= 0 && gy < 64 && gx >= 0 && gx < 64) {
            int gi = base + gy*64 + gx;
            v = __ldg(x + gi) + __ldg(hid + gi);
        }
        patch[py][px] = v;
    }
    __syncthreads();

    float w[49];
    #pragma unroll
    for (int i = 0; i < 49; i++) w[i] = wsm[i];

    int x0 = (tid & 15) << 2;        // 0..60
    int y  = (tid >> 4) << 1;        // 0..30 (two rows y, y+1)
    float bias = dwb[c];
    float a[2][4];
    #pragma unroll
    for (int j = 0; j < 2; j++)
        #pragma unroll
        for (int i = 0; i < 4; i++) a[j][i] = bias;

    #pragma unroll
    for (int r = 0; r < 8; r++) {
        const float* pr = &patch[y + r][x0];
        float4 q0 = *reinterpret_cast<const float4*>(pr);
        float4 q1 = *reinterpret_cast<const float4*>(pr + 4);
        float4 q2 = *reinterpret_cast<const float4*>(pr + 8);
        float e[10] = {q0.x,q0.y,q0.z,q0.w, q1.x,q1.y,q1.z,q1.w, q2.x,q2.y};
        if (r < 7) {
            #pragma unroll
            for (int kx = 0; kx < 7; kx++) {
                float wv = w[r*7 + kx];
                a[0][0] += wv*e[kx];   a[0][1] += wv*e[kx+1];
                a[0][2] += wv*e[kx+2]; a[0][3] += wv*e[kx+3];
            }
        }
        if (r >= 1) {
            #pragma unroll
            for (int kx = 0; kx < 7; kx++) {
                float wv = w[(r-1)*7 + kx];
                a[1][0] += wv*e[kx];   a[1][1] += wv*e[kx+1];
                a[1][2] += wv*e[kx+2]; a[1][3] += wv*e[kx+3];
            }
        }
    }

    *reinterpret_cast<float4*>(g_zconv + base + (ty0+y)*64 + x0) =
        make_float4(a[0][0], a[0][1], a[0][2], a[0][3]);
    *reinterpret_cast<float4*>(g_zconv + base + (ty0+y+1)*64 + x0) =
        make_float4(a[1][0], a[1][1], a[1][2], a[1][3]);

    float s = 0.f, s2 = 0.f;
    #pragma unroll
    for (int j = 0; j < 2; j++)
        #pragma unroll
        for (int i = 0; i < 4; i++) { s += a[j][i]; s2 += a[j][i]*a[j][i]; }
    #pragma unroll
    for (int o = 16; o > 0; o >>= 1) {
        s  += __shfl_xor_sync(~0u, s,  o);
        s2 += __shfl_xor_sync(~0u, s2, o);
    }
    if ((tid & 31) == 0) { redsum[tid>>5] = s; redsq[tid>>5] = s2; }
    __syncthreads();
    if (tid == 0) {
        float S = 0.f, S2 = 0.f;
        #pragma unroll
        for (int i = 0; i < 8; i++) { S += redsum[i]; S2 += redsq[i]; }
        int pi = (bc*2 + strip)*2;
        g_part[pi] = S; g_part[pi+1] = S2;
    }
}

// ---------------------------------------------------------------------------
// Kernel 2: finalize GN stats (96 partials per group now)
// ---------------------------------------------------------------------------
__global__ __launch_bounds__(128) void stats_kernel()
{
    __shared__ float ss[128], sq[128];
    int gidx = blockIdx.x;
    int b = gidx >> 2, g = gidx & 3;
    int base = (b*Cn + g*CPG) * 2 * 2;
    int tid = threadIdx.x;
    float a = 0.f, q = 0.f;
    if (tid < 96) { a = g_part[base + tid*2]; q = g_part[base + tid*2 + 1]; }
    ss[tid] = a; sq[tid] = q;
    __syncthreads();
    for (int st = 64; st > 0; st >>= 1) {
        if (tid < st) { ss[tid] += ss[tid+st]; sq[tid] += sq[tid+st]; }
        __syncthreads();
    }
    if (tid == 0) {
        float inv = 1.0f / (float)NGRP;
        float mu  = ss[0] * inv;
        float var = sq[0] * inv - mu*mu;
        g_mu[gidx]   = mu;
        g_rstd[gidx] = rsqrtf(var + 1e-5f);
    }
}

// ---------------------------------------------------------------------------
// Kernel 3: mma.sync tf32 GEMM, register-pipelined fragments, fused staging
// + LSTM epilogue with hoisted cell loads. Block = 128 px x 768 rows, 512 thr.
// ---------------------------------------------------------------------------
#define WB      98304            // znp: [24 s][128 p][4 t] float2
#define WBUFSZ  32768            // one k32 weight chunk (2048 float4)
#define EPI     (WB + 2*WBUFSZ)  // 163840
#define EPISTR  268
#define GSMEM   (EPI + 32*EPISTR*4)   // 198144

__global__ __launch_bounds__(512,1) void gemm_kernel(
    const float* __restrict__ ctx, const float* __restrict__ cell,
    const float* __restrict__ pwb, float* __restrict__ out)
{
    extern __shared__ __align__(16) char smem[];
    int tid = threadIdx.x;
    int b   = blockIdx.x >> 5;
    int hw0 = (blockIdx.x & 31) << 7;
    int wid = tid >> 5, l = tid & 31;
    int g = l >> 2, t4 = l & 3;
    int wm = wid & 3, wn = wid >> 2;

    // ---- stage znp: zn pairs (k, k+4), GN+FiLM fused, tf32-rounded ----
    {
        int px = tid >> 2;
        int tt = tid & 3;
        const float* zc = g_zconv + (size_t)b*CHW + hw0 + px;
        const float* cs = ctx + (size_t)b*2*CHW + hw0 + px;
        #pragma unroll 8
        for (int i = 0; i < 48; i++) {
            int k = tt + i*4;
            float conv = __ldg(zc + (size_t)k*HW);
            float sc   = __ldg(cs + (size_t)k*HW);
            float bi   = __ldg(cs + (size_t)(k + Cn)*HW);
            int gi = (b << 2) + ((k*683) >> 15);
            float zn = (conv - g_mu[gi])*g_rstd[gi]*(1.0f + sc) + bi;
            unsigned u; asm("cvt.rna.tf32.f32 %0, %1;" : "=r"(u) : "f"(zn));
            int s = k >> 3, h = (k >> 2) & 1;
            reinterpret_cast<float*>(smem)[((s*128 + px)*4 + tt)*2 + h] =
                __uint_as_float(u);
        }
    }

    // ---- prologue: cp.async weight chunk 0 ----
    #pragma unroll
    for (int f = 0; f < 4; f++) {
        int il = tid + f*512;
        int rbl = il >> 9, sh = (il >> 7) & 3, q = il & 127;
        const float4* src = reinterpret_cast<const float4*>(g_wfrag)
                          + (size_t)(rbl*24 + sh)*128 + q;
        unsigned sa = smem_u32(smem + WB + il*16);
        asm volatile("cp.async.cg.shared.global [%0], [%1], 16;"
                     :: "r"(sa), "l"(src));
    }
    asm volatile("cp.async.commit_group;" ::: "memory");

    float D[4][4][4];
    #pragma unroll
    for (int i = 0; i < 4; i++)
        #pragma unroll
        for (int j = 0; j < 4; j++)
            #pragma unroll
            for (int q = 0; q < 4; q++) D[i][j][q] = 0.f;

    for (int gc = 0; gc < 18; gc++) {
        asm volatile("cp.async.wait_group 0;" ::: "memory");
        __syncthreads();
        if (gc + 1 < 18) {
            int g2 = gc + 1;
            int segn = g2/6, ccn = g2 - segn*6;
            #pragma unroll
            for (int f = 0; f < 4; f++) {
                int il = tid + f*512;
                int rbl = il >> 9, sh = (il >> 7) & 3, q = il & 127;
                const float4* src = reinterpret_cast<const float4*>(g_wfrag)
                    + (size_t)((segn*4 + rbl)*24 + ccn*4 + sh)*128 + q;
                unsigned sa = smem_u32(smem + WB + (g2&1)*WBUFSZ + il*16);
                asm volatile("cp.async.cg.shared.global [%0], [%1], 16;"
                             :: "r"(sa), "l"(src));
            }
            asm volatile("cp.async.commit_group;" ::: "memory");
        }
        int cc = gc % 6;
        const char* wb = smem + WB + (gc&1)*WBUFSZ;

        // ---- register-pipelined fragment feed across 4 sh-steps ----
        float4 Abuf[2][4];
        float2 Bbuf[2][4];
        {
            int s0 = cc*4;
            #pragma unroll
            for (int tn = 0; tn < 4; tn++) {
                int p = wn*32 + tn*8 + g;
                Bbuf[0][tn] = *reinterpret_cast<const float2*>(
                                smem + ((s0*128 + p)*4 + t4)*8);
            }
            #pragma unroll
            for (int tm = 0; tm < 4; tm++)
                Abuf[0][tm] = *reinterpret_cast<const float4*>(
                                wb + ((wm*4 + 0)*128 + tm*32 + l)*16);
        }
        #pragma unroll
        for (int sh = 0; sh < 4; sh++) {
            int cur = sh & 1, nxt = cur ^ 1;
            if (sh < 3) {
                int s1 = cc*4 + sh + 1;
                #pragma unroll
                for (int tn = 0; tn < 4; tn++) {
                    int p = wn*32 + tn*8 + g;
                    Bbuf[nxt][tn] = *reinterpret_cast<const float2*>(
                                    smem + ((s1*128 + p)*4 + t4)*8);
                }
                #pragma unroll
                for (int tm = 0; tm < 4; tm++)
                    Abuf[nxt][tm] = *reinterpret_cast<const float4*>(
                                    wb + ((wm*4 + sh + 1)*128 + tm*32 + l)*16);
            }
            #pragma unroll
            for (int tm = 0; tm < 4; tm++)
                #pragma unroll
                for (int tn = 0; tn < 4; tn++)
                    mma_tf32(D[tm][tn], Abuf[cur][tm], Bbuf[cur][tn]);
        }

        if (cc == 5) {
            // ---- epilogue for seg = gc/6: 4 pixel phases of 32 ----
            int seg = gc / 6;
            float* ep = reinterpret_cast<float*>(smem + EPI);
            int chl = tid >> 3;           // 0..63
            int pq  = tid & 7;            // 0..7 -> 4 px each
            int ch  = seg*64 + chl;
            float bfc = __ldg(pwb + ch),       bic = __ldg(pwb + 192 + ch);
            float bgc = __ldg(pwb + 384 + ch), boc = __ldg(pwb + 576 + ch);
            size_t gb0 = (size_t)b*CHW + (size_t)ch*HW + hw0 + pq*4;
            // hoist all 4 phases' cell loads (single latency exposure)
            float4 cellv[4];
            #pragma unroll
            for (int ph = 0; ph < 4; ph++)
                cellv[ph] = __ldg(reinterpret_cast<const float4*>(
                                  cell + gb0 + ph*32));
            #pragma unroll 1
            for (int ph = 0; ph < 4; ph++) {
                if (wn == ph) {
                    #pragma unroll
                    for (int tm = 0; tm < 4; tm++)
                        #pragma unroll
                        for (int tn = 0; tn < 4; tn++) {
                            int row = wm*64 + tm*16 + g;
                            int px  = tn*8 + 2*t4;
                            ep[ px   *EPISTR + row    ] = D[tm][tn][0];
                            ep[(px+1)*EPISTR + row    ] = D[tm][tn][1];
                            ep[ px   *EPISTR + row + 8] = D[tm][tn][2];
                            ep[(px+1)*EPISTR + row + 8] = D[tm][tn][3];
                        }
                }
                __syncthreads();
                size_t gbase = gb0 + ph*32;
                float cold[4] = {cellv[ph].x, cellv[ph].y,
                                 cellv[ph].z, cellv[ph].w};
                float hn[4], cn[4];
                #pragma unroll
                for (int j = 0; j < 4; j++) {
                    float4 gv = *reinterpret_cast<const float4*>(
                                ep + (pq*4 + j)*EPISTR + chl*4);
                    float fv = gv.x + bfc, iv = gv.y + bic;
                    float gg = gv.z + bgc, ov = gv.w + boc;
                    float cv = sigm_f(fv)*cold[j] + sigm_f(iv)*tanh_f(gg);
                    cn[j] = cv;
                    hn[j] = sigm_f(ov) * gelu_exact(cv);
                }
                *reinterpret_cast<float4*>(out + gbase) =
                    make_float4(hn[0], hn[1], hn[2], hn[3]);
                *reinterpret_cast<float4*>(out + NPIX + gbase) =
                    make_float4(cn[0], cn[1], cn[2], cn[3]);
                __syncthreads();
            }
            // reset accumulators for next seg
            #pragma unroll
            for (int i = 0; i < 4; i++)
                #pragma unroll
                for (int j = 0; j < 4; j++)
                    #pragma unroll
                    for (int q = 0; q < 4; q++) D[i][j][q] = 0.f;
        }
    }
}

// ---------------------------------------------------------------------------
extern "C" void kernel_launch(void* const* d_in, const int* in_sizes, int n_in,
                              void* d_out, int out_size)
{
    const float* x      = (const float*)d_in[0];
    const float* hidden = (const float*)d_in[1];
    const float* cell   = (const float*)d_in[2];
    const float* ctx    = (const float*)d_in[3];
    const float* dww    = (const float*)d_in[4];
    const float* dwb    = (const float*)d_in[5];
    const float* pw     = (const float*)d_in[6];
    const float* pwb    = (const float*)d_in[7];
    float* out = (float*)d_out;

    cudaFuncSetAttribute(gemm_kernel,
                         cudaFuncAttributeMaxDynamicSharedMemorySize, GSMEM);

    setup_wt<<<144, 256>>>(pw);
    conv_kernel<<<dim3(Bn*Cn, 2), 256>>>(x, hidden, dww, dwb);
    stats_kernel<<<64, 128>>>();
    gemm_kernel<<<512, 512, GSMEM>>>(ctx, cell, pwb, out);
}